// round 6
// baseline (speedup 1.0000x reference)
#include <cuda_runtime.h>
#include <cstdint>

#define B_DIM 2048
#define I_DIM 512
#define O_DIM 512

#define BM 64
#define BN 64
#define BK 16
#define NTH 128
#define KSPLIT 2
#define KLEN (I_DIM / KSPLIT)   // 256
#define ABSTRIDE 66

// Scratch: precomputed A = 1 - w*s, B = w*(2s-1); partial-product buffer
__device__ float g_A[I_DIM * O_DIM];
__device__ float g_B[I_DIM * O_DIM];
__device__ float g_P[B_DIM * O_DIM];

// ---------- packed f32x2 helpers ----------
__device__ __forceinline__ unsigned long long pack2(float lo, float hi) {
    unsigned long long r;
    asm("mov.b64 %0, {%1, %2};" : "=l"(r) : "f"(lo), "f"(hi));
    return r;
}
__device__ __forceinline__ void unpack2(unsigned long long v, float& lo, float& hi) {
    asm("mov.b64 {%0, %1}, %2;" : "=f"(lo), "=f"(hi) : "l"(v));
}
__device__ __forceinline__ unsigned long long fma2(unsigned long long a, unsigned long long b,
                                                   unsigned long long c) {
    unsigned long long d;
    asm("fma.rn.f32x2 %0, %1, %2, %3;" : "=l"(d) : "l"(a), "l"(b), "l"(c));
    return d;
}
__device__ __forceinline__ unsigned long long mul2(unsigned long long a, unsigned long long b) {
    unsigned long long d;
    asm("mul.rn.f32x2 %0, %1, %2;" : "=l"(d) : "l"(a), "l"(b));
    return d;
}

// ---------- prep: sigmoid + algebraic refactor ----------
__global__ void prep_kernel(const float* __restrict__ wl, const float* __restrict__ sl) {
    int idx = blockIdx.x * blockDim.x + threadIdx.x;
    if (idx < I_DIM * O_DIM) {
        float w = 1.0f / (1.0f + __expf(-wl[idx]));
        float s = 1.0f / (1.0f + __expf(-sl[idx]));
        g_A[idx] = 1.0f - w * s;          // factor = A + x*B
        g_B[idx] = w * (2.0f * s - 1.0f);
    }
}

// ---------- combine: OUT *= g_P ----------
__global__ void combine_kernel(float* __restrict__ OUT) {
    int i = blockIdx.x * blockDim.x + threadIdx.x;
    float4 o = ((const float4*)OUT)[i];
    float4 p = ((const float4*)g_P)[i];
    o.x *= p.x; o.y *= p.y; o.z *= p.z; o.w *= p.w;
    ((float4*)OUT)[i] = o;
}

// ---------- main: product-GEMM, 64x64 tile, 16x2 microtile, k-split partials ----------
__global__ __launch_bounds__(NTH, 4)
void fuzzy_prod_kernel(const float* __restrict__ X, float* __restrict__ OUT) {
    __shared__ float Xs[2][BK][BM];
    __shared__ float As[2][BK * ABSTRIDE];
    __shared__ float Bs[2][BK * ABSTRIDE];

    const int tid = threadIdx.x;
    const int tx  = tid & 31;      // o-pair: o = 2tx, 2tx+1
    const int ty  = tid >> 5;      // b-group: rows ty*16 .. ty*16+15
    const int bn0 = blockIdx.x * BN;
    const int bm0 = blockIdx.y * BM;
    const int k0  = blockIdx.z * KLEN;
    float* dst = (blockIdx.z == 0) ? OUT : g_P;

    // X loader: 64 rows x 16 k -> 8 floats (2 float4) per thread
    const int xrow = tid >> 1;           // 0..63
    const int xk8  = (tid & 1) * 8;      // 0 or 8
    // A/B loader: 16 k-rows x 64 o -> rows arow, arow+8, one float4 each
    const int arow = tid >> 4;           // 0..7
    const int acol = (tid & 15) * 4;     // 0..60

    const unsigned long long ONE2 = pack2(1.0f, 1.0f);
    unsigned long long acc[8][2];
#pragma unroll
    for (int p = 0; p < 8; p++) { acc[p][0] = ONE2; acc[p][1] = ONE2; }

    // ---- prologue: fill buffer 0 ----
    {
        float4 x0 = *(const float4*)&X[(bm0 + xrow) * I_DIM + k0 + xk8];
        float4 x1 = *(const float4*)&X[(bm0 + xrow) * I_DIM + k0 + xk8 + 4];
        float4 a0 = *(const float4*)&g_A[(k0 + arow) * O_DIM + bn0 + acol];
        float4 a1 = *(const float4*)&g_A[(k0 + arow + 8) * O_DIM + bn0 + acol];
        float4 b0 = *(const float4*)&g_B[(k0 + arow) * O_DIM + bn0 + acol];
        float4 b1 = *(const float4*)&g_B[(k0 + arow + 8) * O_DIM + bn0 + acol];
        float xv[8] = {x0.x, x0.y, x0.z, x0.w, x1.x, x1.y, x1.z, x1.w};
#pragma unroll
        for (int j = 0; j < 8; j++) {
            int k = xk8 + j;
            Xs[0][k][xrow ^ (8 * ((k >> 2) & 3))] = xv[j];
        }
        *(float2*)&As[0][arow * ABSTRIDE + acol]           = make_float2(a0.x, a0.y);
        *(float2*)&As[0][arow * ABSTRIDE + acol + 2]       = make_float2(a0.z, a0.w);
        *(float2*)&As[0][(arow + 8) * ABSTRIDE + acol]     = make_float2(a1.x, a1.y);
        *(float2*)&As[0][(arow + 8) * ABSTRIDE + acol + 2] = make_float2(a1.z, a1.w);
        *(float2*)&Bs[0][arow * ABSTRIDE + acol]           = make_float2(b0.x, b0.y);
        *(float2*)&Bs[0][arow * ABSTRIDE + acol + 2]       = make_float2(b0.z, b0.w);
        *(float2*)&Bs[0][(arow + 8) * ABSTRIDE + acol]     = make_float2(b1.x, b1.y);
        *(float2*)&Bs[0][(arow + 8) * ABSTRIDE + acol + 2] = make_float2(b1.z, b1.w);
    }
    __syncthreads();

    int buf = 0;
    for (int kt = k0; kt < k0 + KLEN; kt += BK) {
        const int nxt = buf ^ 1;
        const bool has_next = (kt + BK < k0 + KLEN);
        float4 xn0, xn1, an0, an1, bn0v, bn1v;
        if (has_next) {  // register-staged prefetch overlaps compute
            xn0  = *(const float4*)&X[(bm0 + xrow) * I_DIM + (kt + BK) + xk8];
            xn1  = *(const float4*)&X[(bm0 + xrow) * I_DIM + (kt + BK) + xk8 + 4];
            an0  = *(const float4*)&g_A[(kt + BK + arow) * O_DIM + bn0 + acol];
            an1  = *(const float4*)&g_A[(kt + BK + arow + 8) * O_DIM + bn0 + acol];
            bn0v = *(const float4*)&g_B[(kt + BK + arow) * O_DIM + bn0 + acol];
            bn1v = *(const float4*)&g_B[(kt + BK + arow + 8) * O_DIM + bn0 + acol];
        }

#pragma unroll
        for (int k = 0; k < BK; k++) {
            const int sw = 8 * ((k >> 2) & 3);
            float2 av = *(const float2*)&As[buf][k * ABSTRIDE + tx * 2];
            float2 bv = *(const float2*)&Bs[buf][k * ABSTRIDE + tx * 2];
            unsigned long long a0d = pack2(av.x, av.x);
            unsigned long long a1d = pack2(av.y, av.y);
            unsigned long long b0d = pack2(bv.x, bv.x);
            unsigned long long b1d = pack2(bv.y, bv.y);
#pragma unroll
            for (int j = 0; j < 4; j++) {
                // warp-broadcast float4 (all lanes same address)
                float4 xv = *(const float4*)&Xs[buf][k][(ty * 16 + 4 * j) ^ sw];
                unsigned long long xp0 = pack2(xv.x, xv.y);
                unsigned long long xp1 = pack2(xv.z, xv.w);
                acc[2 * j][0]     = mul2(acc[2 * j][0],     fma2(xp0, b0d, a0d));
                acc[2 * j][1]     = mul2(acc[2 * j][1],     fma2(xp0, b1d, a1d));
                acc[2 * j + 1][0] = mul2(acc[2 * j + 1][0], fma2(xp1, b0d, a0d));
                acc[2 * j + 1][1] = mul2(acc[2 * j + 1][1], fma2(xp1, b1d, a1d));
            }
        }

        if (has_next) {
            float xv[8] = {xn0.x, xn0.y, xn0.z, xn0.w, xn1.x, xn1.y, xn1.z, xn1.w};
#pragma unroll
            for (int j = 0; j < 8; j++) {
                int k = xk8 + j;
                Xs[nxt][k][xrow ^ (8 * ((k >> 2) & 3))] = xv[j];
            }
            *(float2*)&As[nxt][arow * ABSTRIDE + acol]           = make_float2(an0.x, an0.y);
            *(float2*)&As[nxt][arow * ABSTRIDE + acol + 2]       = make_float2(an0.z, an0.w);
            *(float2*)&As[nxt][(arow + 8) * ABSTRIDE + acol]     = make_float2(an1.x, an1.y);
            *(float2*)&As[nxt][(arow + 8) * ABSTRIDE + acol + 2] = make_float2(an1.z, an1.w);
            *(float2*)&Bs[nxt][arow * ABSTRIDE + acol]           = make_float2(bn0v.x, bn0v.y);
            *(float2*)&Bs[nxt][arow * ABSTRIDE + acol + 2]       = make_float2(bn0v.z, bn0v.w);
            *(float2*)&Bs[nxt][(arow + 8) * ABSTRIDE + acol]     = make_float2(bn1v.x, bn1v.y);
            *(float2*)&Bs[nxt][(arow + 8) * ABSTRIDE + acol + 2] = make_float2(bn1v.z, bn1v.w);
        }
        __syncthreads();
        buf = nxt;
    }

    // ---- epilogue: 16 coalesced STG.64 per thread ----
#pragma unroll
    for (int p = 0; p < 8; p++) {
        float e0, e1, f0, f1;
        unpack2(acc[p][0], e0, e1);   // col 2tx,   rows 2p, 2p+1
        unpack2(acc[p][1], f0, f1);   // col 2tx+1
        const int row = bm0 + ty * 16 + 2 * p;
        *(float2*)&dst[row * O_DIM + bn0 + tx * 2]       = make_float2(e0, f0);
        *(float2*)&dst[(row + 1) * O_DIM + bn0 + tx * 2] = make_float2(e1, f1);
    }
}

extern "C" void kernel_launch(void* const* d_in, const int* in_sizes, int n_in,
                              void* d_out, int out_size) {
    const float* x  = (const float*)d_in[0];   // (2048, 512)
    const float* wl = (const float*)d_in[1];   // (512, 512)
    const float* sl = (const float*)d_in[2];   // (512, 512)
    float* out = (float*)d_out;                // (2048, 512)

    prep_kernel<<<(I_DIM * O_DIM + 255) / 256, 256>>>(wl, sl);

    dim3 grid(O_DIM / BN, B_DIM / BM, KSPLIT);  // (8, 32, 2) = 512 CTAs
    fuzzy_prod_kernel<<<grid, NTH>>>(x, out);

    combine_kernel<<<(B_DIM * O_DIM / 4) / 256, 256>>>(out);
}

// round 8
// speedup vs baseline: 1.5603x; 1.5603x over previous
#include <cuda_runtime.h>
#include <cstdint>

#define B_DIM 2048
#define I_DIM 512
#define O_DIM 512

#define BM 64
#define BN 64
#define BK 16
#define NTH 128
#define KSPLIT 2
#define KLEN (I_DIM / KSPLIT)   // 256
#define ABSTRIDE 68             // multiple of 4 -> 16B-aligned rows for cp.async

// Scratch: precomputed A = 1 - w*s, B = w*(2s-1); partial-product buffer
__device__ float g_A[I_DIM * O_DIM];
__device__ float g_B[I_DIM * O_DIM];
__device__ float g_P[B_DIM * O_DIM];

// ---------- packed f32x2 helpers ----------
__device__ __forceinline__ unsigned long long pack2(float lo, float hi) {
    unsigned long long r;
    asm("mov.b64 %0, {%1, %2};" : "=l"(r) : "f"(lo), "f"(hi));
    return r;
}
__device__ __forceinline__ void unpack2(unsigned long long v, float& lo, float& hi) {
    asm("mov.b64 {%0, %1}, %2;" : "=f"(lo), "=f"(hi) : "l"(v));
}
__device__ __forceinline__ unsigned long long fma2(unsigned long long a, unsigned long long b,
                                                   unsigned long long c) {
    unsigned long long d;
    asm("fma.rn.f32x2 %0, %1, %2, %3;" : "=l"(d) : "l"(a), "l"(b), "l"(c));
    return d;
}
__device__ __forceinline__ unsigned long long mul2(unsigned long long a, unsigned long long b) {
    unsigned long long d;
    asm("mul.rn.f32x2 %0, %1, %2;" : "=l"(d) : "l"(a), "l"(b));
    return d;
}

// ---------- cp.async helpers ----------
__device__ __forceinline__ void cp_async16(uint32_t smem_addr, const void* gptr) {
    asm volatile("cp.async.cg.shared.global [%0], [%1], 16;" :: "r"(smem_addr), "l"(gptr));
}
__device__ __forceinline__ void cp_commit() { asm volatile("cp.async.commit_group;"); }
__device__ __forceinline__ void cp_wait0()  { asm volatile("cp.async.wait_group 0;"); }

// ---------- prep: sigmoid + algebraic refactor (float4) ----------
__global__ void prep_kernel(const float* __restrict__ wl, const float* __restrict__ sl) {
    int i = blockIdx.x * blockDim.x + threadIdx.x;   // float4 index
    float4 w4 = ((const float4*)wl)[i];
    float4 s4 = ((const float4*)sl)[i];
    float4 a4, b4;
    {
        float w, s;
        w = 1.0f / (1.0f + __expf(-w4.x)); s = 1.0f / (1.0f + __expf(-s4.x));
        a4.x = 1.0f - w * s; b4.x = w * (2.0f * s - 1.0f);
        w = 1.0f / (1.0f + __expf(-w4.y)); s = 1.0f / (1.0f + __expf(-s4.y));
        a4.y = 1.0f - w * s; b4.y = w * (2.0f * s - 1.0f);
        w = 1.0f / (1.0f + __expf(-w4.z)); s = 1.0f / (1.0f + __expf(-s4.z));
        a4.z = 1.0f - w * s; b4.z = w * (2.0f * s - 1.0f);
        w = 1.0f / (1.0f + __expf(-w4.w)); s = 1.0f / (1.0f + __expf(-s4.w));
        a4.w = 1.0f - w * s; b4.w = w * (2.0f * s - 1.0f);
    }
    ((float4*)g_A)[i] = a4;
    ((float4*)g_B)[i] = b4;
}

// ---------- combine: OUT *= g_P (float4) ----------
__global__ void combine_kernel(float* __restrict__ OUT) {
    int i = blockIdx.x * blockDim.x + threadIdx.x;
    float4 o = ((const float4*)OUT)[i];
    float4 p = ((const float4*)g_P)[i];
    o.x *= p.x; o.y *= p.y; o.z *= p.z; o.w *= p.w;
    ((float4*)OUT)[i] = o;
}

// ---------- main: product-GEMM, 64x64 tile, 16x2 microtile, cp.async A/B ----------
__global__ __launch_bounds__(NTH, 4)
void fuzzy_prod_kernel(const float* __restrict__ X, float* __restrict__ OUT) {
    __shared__ __align__(16) float Xs[2][BK][BM];
    __shared__ __align__(16) float As[2][BK * ABSTRIDE];
    __shared__ __align__(16) float Bs[2][BK * ABSTRIDE];

    const int tid = threadIdx.x;
    const int tx  = tid & 31;      // o-pair: o = 2tx, 2tx+1
    const int ty  = tid >> 5;      // b-group: rows ty*16 .. ty*16+15
    const int bn0 = blockIdx.x * BN;
    const int bm0 = blockIdx.y * BM;
    const int k0  = blockIdx.z * KLEN;
    float* dst = (blockIdx.z == 0) ? OUT : g_P;

    // X loader: 64 rows x 16 k -> 8 floats (2 float4) per thread
    const int xrow = tid >> 1;           // 0..63
    const int xk8  = (tid & 1) * 8;      // 0 or 8
    // A/B cp.async loader: 16 rows x 64 floats = 256 x 16B chunks; 2 chunks/thread each
    const int c0r = tid >> 4;            // rows 0..7   (chunk tid)
    const int c0c = (tid & 15) * 4;      // col 0..60
    // second chunk: rows 8..15, same col

    const float* gA0 = &g_A[(k0 + c0r) * O_DIM + bn0 + c0c];
    const float* gA1 = &g_A[(k0 + c0r + 8) * O_DIM + bn0 + c0c];
    const float* gB0 = &g_B[(k0 + c0r) * O_DIM + bn0 + c0c];
    const float* gB1 = &g_B[(k0 + c0r + 8) * O_DIM + bn0 + c0c];
    const uint32_t sA0 = (uint32_t)__cvta_generic_to_shared(&As[0][c0r * ABSTRIDE + c0c]);
    const uint32_t sA1 = (uint32_t)__cvta_generic_to_shared(&As[0][(c0r + 8) * ABSTRIDE + c0c]);
    const uint32_t sB0 = (uint32_t)__cvta_generic_to_shared(&Bs[0][c0r * ABSTRIDE + c0c]);
    const uint32_t sB1 = (uint32_t)__cvta_generic_to_shared(&Bs[0][(c0r + 8) * ABSTRIDE + c0c]);
    const uint32_t bufBytesAB = (uint32_t)(BK * ABSTRIDE * sizeof(float));

    const unsigned long long ONE2 = pack2(1.0f, 1.0f);
    unsigned long long acc[8][2];
#pragma unroll
    for (int p = 0; p < 8; p++) { acc[p][0] = ONE2; acc[p][1] = ONE2; }

    // ---- prologue: fill buffer 0 ----
    {
        cp_async16(sA0, gA0);
        cp_async16(sA1, gA1);
        cp_async16(sB0, gB0);
        cp_async16(sB1, gB1);
        cp_commit();
        float4 x0 = *(const float4*)&X[(bm0 + xrow) * I_DIM + k0 + xk8];
        float4 x1 = *(const float4*)&X[(bm0 + xrow) * I_DIM + k0 + xk8 + 4];
        float xv[8] = {x0.x, x0.y, x0.z, x0.w, x1.x, x1.y, x1.z, x1.w};
#pragma unroll
        for (int j = 0; j < 8; j++) {
            int k = xk8 + j;
            Xs[0][k][xrow ^ (8 * ((k >> 2) & 3))] = xv[j];
        }
        cp_wait0();
    }
    __syncthreads();

    int buf = 0;
    for (int kt = k0; kt < k0 + KLEN; kt += BK) {
        const int nxt = buf ^ 1;
        const bool has_next = (kt + BK < k0 + KLEN);
        const int koff = kt - k0 + BK;   // offset of next tile from k0
        float4 xn0, xn1;
        if (has_next) {
            // cp.async A/B for next tile (fire-and-forget, overlaps compute)
            const uint32_t soff = (nxt ? bufBytesAB : 0);
            cp_async16(sA0 + soff, gA0 + koff * O_DIM);
            cp_async16(sA1 + soff, gA1 + koff * O_DIM);
            cp_async16(sB0 + soff, gB0 + koff * O_DIM);
            cp_async16(sB1 + soff, gB1 + koff * O_DIM);
            cp_commit();
            xn0 = *(const float4*)&X[(bm0 + xrow) * I_DIM + (kt + BK) + xk8];
            xn1 = *(const float4*)&X[(bm0 + xrow) * I_DIM + (kt + BK) + xk8 + 4];
        }

#pragma unroll
        for (int k = 0; k < BK; k++) {
            const int sw = 8 * ((k >> 2) & 3);
            float2 av = *(const float2*)&As[buf][k * ABSTRIDE + tx * 2];
            float2 bv = *(const float2*)&Bs[buf][k * ABSTRIDE + tx * 2];
            unsigned long long a0d = pack2(av.x, av.x);
            unsigned long long a1d = pack2(av.y, av.y);
            unsigned long long b0d = pack2(bv.x, bv.x);
            unsigned long long b1d = pack2(bv.y, bv.y);
#pragma unroll
            for (int j = 0; j < 4; j++) {
                // warp-broadcast float4 (all lanes same address)
                float4 xv = *(const float4*)&Xs[buf][k][(ty * 16 + 4 * j) ^ sw];
                unsigned long long xp0 = pack2(xv.x, xv.y);
                unsigned long long xp1 = pack2(xv.z, xv.w);
                acc[2 * j][0]     = mul2(acc[2 * j][0],     fma2(xp0, b0d, a0d));
                acc[2 * j][1]     = mul2(acc[2 * j][1],     fma2(xp0, b1d, a1d));
                acc[2 * j + 1][0] = mul2(acc[2 * j + 1][0], fma2(xp1, b0d, a0d));
                acc[2 * j + 1][1] = mul2(acc[2 * j + 1][1], fma2(xp1, b1d, a1d));
            }
        }

        if (has_next) {
            float xv[8] = {xn0.x, xn0.y, xn0.z, xn0.w, xn1.x, xn1.y, xn1.z, xn1.w};
#pragma unroll
            for (int j = 0; j < 8; j++) {
                int k = xk8 + j;
                Xs[nxt][k][xrow ^ (8 * ((k >> 2) & 3))] = xv[j];
            }
            cp_wait0();
        }
        __syncthreads();
        buf = nxt;
    }

    // ---- epilogue: 16 coalesced STG.64 per thread ----
#pragma unroll
    for (int p = 0; p < 8; p++) {
        float e0, e1, f0, f1;
        unpack2(acc[p][0], e0, e1);   // col 2tx,   rows 2p, 2p+1
        unpack2(acc[p][1], f0, f1);   // col 2tx+1
        const int row = bm0 + ty * 16 + 2 * p;
        *(float2*)&dst[row * O_DIM + bn0 + tx * 2]       = make_float2(e0, f0);
        *(float2*)&dst[(row + 1) * O_DIM + bn0 + tx * 2] = make_float2(e1, f1);
    }
}

extern "C" void kernel_launch(void* const* d_in, const int* in_sizes, int n_in,
                              void* d_out, int out_size) {
    const float* x  = (const float*)d_in[0];   // (2048, 512)
    const float* wl = (const float*)d_in[1];   // (512, 512)
    const float* sl = (const float*)d_in[2];   // (512, 512)
    float* out = (float*)d_out;                // (2048, 512)

    prep_kernel<<<(I_DIM * O_DIM / 4) / 256, 256>>>(wl, sl);

    dim3 grid(O_DIM / BN, B_DIM / BM, KSPLIT);  // (8, 32, 2) = 512 CTAs
    fuzzy_prod_kernel<<<grid, NTH>>>(x, out);

    combine_kernel<<<(B_DIM * O_DIM / 4) / 256, 256>>>(out);
}